// round 16
// baseline (speedup 1.0000x reference)
#include <cuda_runtime.h>
#include <cuda_fp16.h>
#include <cstdint>

// ---------------- problem constants ----------------
#define SLABS      128                  // B*H = 4*32
#define TL         1024
#define HD         128
#define SLAB_ELEMS (TL * HD)
#define TOT        (SLABS * SLAB_ELEMS) // 16,777,216 elements

// ---------------- device scratch ----------------
__device__ __align__(16) __half g_q1[TOT];   // quantized x1, row-major [slab][t][k]
__device__ __align__(16) __half g_S [TOT];   // S = q2 @ H_raw, row-major [slab][s][k]
__device__ float     g_c [SLABS * TL];       // c[t] = q1[t,:]·mu
__device__ float     g_part1[SLABS * 32];    // amax1 partials (written every call)
__device__ float     g_part2[SLABS * 128];   // amax2 partials (written every call)
__device__ unsigned  g_amax1[SLABS];         // reduced amax (published by quant blocks)
__device__ unsigned  g_amax2[SLABS];

// ---------------- PTX helpers ----------------
__device__ __forceinline__ uint32_t smem_u32(const void* p) {
    uint32_t a;
    asm("{ .reg .u64 t; cvta.to.shared.u64 t, %1; cvt.u32.u64 %0, t; }" : "=r"(a) : "l"(p));
    return a;
}
#define CP_ASYNC16(dst, src) \
    asm volatile("cp.async.cg.shared.global [%0], [%1], 16;" :: "r"((uint32_t)(dst)), "l"(src))
#define CP_COMMIT() asm volatile("cp.async.commit_group;" ::: "memory")
#define CP_WAIT0()  asm volatile("cp.async.wait_group 0;"  ::: "memory")

__device__ __forceinline__ void ldsm4(uint32_t& r0, uint32_t& r1, uint32_t& r2, uint32_t& r3,
                                      uint32_t addr) {
    asm volatile("ldmatrix.sync.aligned.m8n8.x4.shared.b16 {%0,%1,%2,%3}, [%4];"
                 : "=r"(r0), "=r"(r1), "=r"(r2), "=r"(r3) : "r"(addr));
}
__device__ __forceinline__ void mma16816(float c[4], uint32_t a0, uint32_t a1, uint32_t a2,
                                         uint32_t a3, uint32_t b0, uint32_t b1) {
    asm volatile(
        "mma.sync.aligned.m16n8k16.row.col.f32.f16.f16.f32 "
        "{%0,%1,%2,%3}, {%4,%5,%6,%7}, {%8,%9}, {%0,%1,%2,%3};"
        : "+f"(c[0]), "+f"(c[1]), "+f"(c[2]), "+f"(c[3])
        : "r"(a0), "r"(a1), "r"(a2), "r"(a3), "r"(b0), "r"(b1));
}

// ---------------- reduction helpers ----------------
__device__ __forceinline__ float warp_max(float m) {
#pragma unroll
    for (int s = 16; s; s >>= 1) m = fmaxf(m, __shfl_xor_sync(0xffffffffu, m, s));
    return m;
}
__device__ __forceinline__ float warp_sum(float v) {
#pragma unroll
    for (int s = 16; s; s >>= 1) v += __shfl_xor_sync(0xffffffffu, v, s);
    return v;
}

// FWHT 128, contiguous layout: lane l holds a[k] = v[4l + k].
// Strides 1,2 register-local; strides 4..64 via shfl. FFMA(+/-1) exact.
__device__ __forceinline__ void fwht128c(float a[4], int l) {
    float t;
    t = a[0]; a[0] = t + a[1]; a[1] = t - a[1];   // stride 1
    t = a[2]; a[2] = t + a[3]; a[3] = t - a[3];
    t = a[0]; a[0] = t + a[2]; a[2] = t - a[2];   // stride 2
    t = a[1]; a[1] = t + a[3]; a[3] = t - a[3];
#pragma unroll
    for (int s = 1; s <= 16; s <<= 1) {           // strides 4..64
        float sgn = __int_as_float((l & s) ? 0xBF800000u : 0x3F800000u);
#pragma unroll
        for (int k = 0; k < 4; k++) {
            float p = __shfl_xor_sync(0xffffffffu, a[k], s);
            a[k] = __fmaf_rn(sgn, a[k], p);
        }
    }
}

// ---------------- prep kernels ----------------
// fused amax: blocks [0,4096) -> amax1(x1) partials; [4096,20480) -> amax2 partials.
// Plain stores into dedicated slots -> NO init kernel, NO atomics.
__global__ __launch_bounds__(256) void amax_fused(const float* __restrict__ x1,
                                                  const float* __restrict__ x2,
                                                  const float* __restrict__ mu) {
    __shared__ float red[8];
    int bid = blockIdx.x;
    int l = threadIdx.x & 31;
    if (bid < 4096) {
        int slab = bid >> 5, part = bid & 31;
        const float4* p = reinterpret_cast<const float4*>(x1 + (size_t)slab * SLAB_ELEMS)
                          + (size_t)part * 1024 + threadIdx.x;
        float m = 0.f;
#pragma unroll
        for (int i = 0; i < 4; i++) {
            float4 v = p[i * 256];
            m = fmaxf(m, fmaxf(fmaxf(fabsf(v.x), fabsf(v.y)), fmaxf(fabsf(v.z), fabsf(v.w))));
        }
        m = warp_max(m);
        if (l == 0) red[threadIdx.x >> 5] = m;
        __syncthreads();
        if (threadIdx.x == 0) {
            float mm = red[0];
#pragma unroll
            for (int i = 1; i < 8; i++) mm = fmaxf(mm, red[i]);
            g_part1[slab * 32 + part] = mm;
        }
    } else {
        int rb = bid - 4096;                      // 0..16383, 8 rows per block
        int r = (rb << 3) + (threadIdx.x >> 5);
        int slab = r >> 10, h = slab & 31;
        float4 xv = reinterpret_cast<const float4*>(x2 + (size_t)r * HD)[l];
        float4 mv = reinterpret_cast<const float4*>(mu + h * HD)[l];
        float a[4] = { xv.x - mv.x, xv.y - mv.y, xv.z - mv.z, xv.w - mv.w };
        fwht128c(a, l);
        float inv = __fdiv_rn(1.0f, __fsqrt_rn(128.0f));
        float m = 0.f;
#pragma unroll
        for (int k = 0; k < 4; k++) m = fmaxf(m, fabsf(__fmul_rn(a[k], inv)));
        m = warp_max(m);
        if (l == 0) red[threadIdx.x >> 5] = m;
        __syncthreads();
        if (threadIdx.x == 0) {
            float mm = red[0];
#pragma unroll
            for (int i = 1; i < 8; i++) mm = fmaxf(mm, red[i]);
            g_part2[slab * 128 + (rb & 127)] = mm;   // 128 blocks per slab
        }
    }
}

// fused quant: blocks [0,8192) -> quant1 (2 rows/warp); [8192,24576) -> quant2S.
// Each block reduces its slab's partials at entry (exact, order-free fmax).
__global__ __launch_bounds__(256) void quant_fused(const float* __restrict__ x1,
                                                   const float* __restrict__ x2,
                                                   const float* __restrict__ mu) {
    __shared__ float sred[8];
    __shared__ float samax;
    int bid = blockIdx.x;
    int l = threadIdx.x & 31;
    if (bid < 8192) {
        int r0 = (bid << 4) + ((threadIdx.x >> 5) << 1);
        int slab = r0 >> 10, h = slab & 31;
        // issue input loads first (independent of the gate reduction)
        float4 v0 = reinterpret_cast<const float4*>(x1 + (size_t)r0 * HD)[l];
        float4 v1 = reinterpret_cast<const float4*>(x1 + (size_t)(r0 + 1) * HD)[l];
        float4 m = reinterpret_cast<const float4*>(mu + h * HD)[l];
        // reduce 32 partials
        if (threadIdx.x < 32) {
            float v = g_part1[slab * 32 + threadIdx.x];
            v = warp_max(v);
            if (threadIdx.x == 0) {
                samax = v;
                g_amax1[slab] = __float_as_uint(v);   // publish for GEMM
            }
        }
        __syncthreads();
        float rs = __fdiv_rn(127.0f, fmaxf(samax, 1e-8f));
        float4 q0, q1;
        q0.x = fminf(fmaxf(rintf(__fmul_rn(v0.x, rs)), -128.f), 127.f);
        q0.y = fminf(fmaxf(rintf(__fmul_rn(v0.y, rs)), -128.f), 127.f);
        q0.z = fminf(fmaxf(rintf(__fmul_rn(v0.z, rs)), -128.f), 127.f);
        q0.w = fminf(fmaxf(rintf(__fmul_rn(v0.w, rs)), -128.f), 127.f);
        q1.x = fminf(fmaxf(rintf(__fmul_rn(v1.x, rs)), -128.f), 127.f);
        q1.y = fminf(fmaxf(rintf(__fmul_rn(v1.y, rs)), -128.f), 127.f);
        q1.z = fminf(fmaxf(rintf(__fmul_rn(v1.z, rs)), -128.f), 127.f);
        q1.w = fminf(fmaxf(rintf(__fmul_rn(v1.w, rs)), -128.f), 127.f);
        float p0 = __fmaf_rn(q0.x, m.x, __fmaf_rn(q0.y, m.y, __fmaf_rn(q0.z, m.z, q0.w * m.w)));
        float p1 = __fmaf_rn(q1.x, m.x, __fmaf_rn(q1.y, m.y, __fmaf_rn(q1.z, m.z, q1.w * m.w)));
        p0 = warp_sum(p0);
        p1 = warp_sum(p1);
        if (l == 0) { g_c[r0] = p0; g_c[r0 + 1] = p1; }
        __half2 a0 = __floats2half2_rn(q0.x, q0.y), a1 = __floats2half2_rn(q0.z, q0.w);
        __half2 b0 = __floats2half2_rn(q1.x, q1.y), b1 = __floats2half2_rn(q1.z, q1.w);
        uint2 w0, w1;
        w0.x = *reinterpret_cast<uint32_t*>(&a0); w0.y = *reinterpret_cast<uint32_t*>(&a1);
        w1.x = *reinterpret_cast<uint32_t*>(&b0); w1.y = *reinterpret_cast<uint32_t*>(&b1);
        reinterpret_cast<uint2*>(g_q1 + (size_t)r0 * HD)[l] = w0;
        reinterpret_cast<uint2*>(g_q1 + (size_t)(r0 + 1) * HD)[l] = w1;
    } else {
        int r = ((bid - 8192) << 3) + (threadIdx.x >> 5);
        int slab = r >> 10, h = slab & 31;
        float4 xv = reinterpret_cast<const float4*>(x2 + (size_t)r * HD)[l];
        float4 mv = reinterpret_cast<const float4*>(mu + h * HD)[l];
        // reduce 128 partials
        if (threadIdx.x < 128) {
            float v = g_part2[slab * 128 + threadIdx.x];
            v = warp_max(v);
            if ((threadIdx.x & 31) == 0) sred[threadIdx.x >> 5] = v;
        }
        __syncthreads();
        if (threadIdx.x == 0) {
            float v = fmaxf(fmaxf(sred[0], sred[1]), fmaxf(sred[2], sred[3]));
            samax = v;
            g_amax2[slab] = __float_as_uint(v);       // publish for GEMM
        }
        __syncthreads();
        float rs = __fdiv_rn(7.0f, fmaxf(samax, 1e-8f));
        float a[4] = { xv.x - mv.x, xv.y - mv.y, xv.z - mv.z, xv.w - mv.w };
        fwht128c(a, l);
        float inv = __fdiv_rn(1.0f, __fsqrt_rn(128.0f));
        float f = __fmul_rn(inv, rs);
#pragma unroll
        for (int k = 0; k < 4; k++)
            a[k] = fminf(fmaxf(rintf(__fmul_rn(a[k], f)), -8.f), 7.f);
        fwht128c(a, l);   // S integers, |S| <= 1024; lane already contiguous
        __half2 p0 = __floats2half2_rn(a[0], a[1]);
        __half2 p1 = __floats2half2_rn(a[2], a[3]);
        uint2 w;
        w.x = *reinterpret_cast<uint32_t*>(&p0);
        w.y = *reinterpret_cast<uint32_t*>(&p1);
        reinterpret_cast<uint2*>(g_S + (size_t)r * HD)[l] = w;
    }
}

// ---------------- GEMM: out[t,s] = alpha*(q1 @ S^T) + scale1*c[t] ----------------
// R8 configuration (measured best: 146.2-146.8us). FROZEN.
#define SMEM_BYTES (81920 + 1024)

__global__ __launch_bounds__(256, 2) void gemm_kernel(float* __restrict__ out) {
    extern __shared__ uint8_t smem_raw[];
    uint32_t sbase = (smem_u32(smem_raw) + 1023u) & ~1023u;
    uint32_t sA = sbase;                       // 16KB
    uint32_t sB = sbase + 16384u;              // 2 x 32KB

    int tid = threadIdx.x, l = tid & 31, wid = tid >> 5;
    int wm = wid >> 2, wn = wid & 3;           // wm 0..1, wn 0..3
    int strip = blockIdx.x, slab = blockIdx.y;

    const uint8_t* gA = reinterpret_cast<const uint8_t*>(g_q1)
                      + ((size_t)slab << 18) + (size_t)strip * 16384u;
    const uint8_t* gB = reinterpret_cast<const uint8_t*>(g_S) + ((size_t)slab << 18);

    // ---- stage A (64 rows x 256B) + B0 ----
#pragma unroll
    for (int p = 0; p < 4; p++) {
        int idx = p * 256 + tid;
        int r = idx >> 4, c = idx & 15;
        CP_ASYNC16(sA + r * 256 + ((c ^ (r & 7)) << 4), gA + (size_t)idx * 16);
    }
#pragma unroll
    for (int p = 0; p < 8; p++) {
        int idx = p * 256 + tid;
        int r = idx >> 4, c = idx & 15;
        CP_ASYNC16(sB + r * 256 + ((c ^ (r & 7)) << 4), gB + (size_t)idx * 16);
    }
    CP_COMMIT();

    // ---- scales / per-row correction ----
    float scale1 = __fdiv_rn(fmaxf(__uint_as_float(g_amax1[slab]), 1e-8f), 127.0f);
    float scale2 = __fdiv_rn(fmaxf(__uint_as_float(g_amax2[slab]), 1e-8f), 7.0f);
    float alpha  = scale1 * scale2 * __fdiv_rn(1.0f, __fsqrt_rn(128.0f));

    float ct[2][2];
#pragma unroll
    for (int mt = 0; mt < 2; mt++) {
        int t0 = strip * 64 + wm * 32 + mt * 16 + (l >> 2);
        ct[mt][0] = scale1 * __ldg(&g_c[slab * 1024 + t0]);
        ct[mt][1] = scale1 * __ldg(&g_c[slab * 1024 + t0 + 8]);
    }

    int hi = (l >> 4);
    uint32_t aAddr[2], aSw[2];
#pragma unroll
    for (int mt = 0; mt < 2; mt++) {
        int r = wm * 32 + mt * 16 + (l & 15);
        aAddr[mt] = sA + r * 256;
        aSw[mt] = (uint32_t)(r & 7);
    }
    uint32_t bOff[2], bSw[2];
#pragma unroll
    for (int np = 0; np < 2; np++) {
        int r = wn * 32 + np * 16 + (l & 15);
        bOff[np] = (uint32_t)(r * 256);
        bSw[np] = (uint32_t)(r & 7);
    }

    // ---- wait for A+B0; hoist A fragments for ksteps 0..3 (32 regs) ----
    CP_WAIT0();
    __syncthreads();

    uint32_t areg[2][4][4];
#pragma unroll
    for (int mt = 0; mt < 2; mt++)
#pragma unroll
        for (int ks = 0; ks < 4; ks++) {
            uint32_t c16 = (uint32_t)(2 * ks + hi);
            ldsm4(areg[mt][ks][0], areg[mt][ks][1], areg[mt][ks][2], areg[mt][ks][3],
                  aAddr[mt] + ((c16 ^ aSw[mt]) << 4));
        }

    float* outp = out + ((size_t)slab << 20);

    for (int it = 0; it < 8; it++) {
        // prefetch next B tile into the other buffer
        if (it + 1 < 8) {
            uint32_t dstb = sB + (uint32_t)((it + 1) & 1) * 32768u;
            const uint8_t* srcb = gB + ((size_t)(it + 1) << 15);
#pragma unroll
            for (int p = 0; p < 8; p++) {
                int idx = p * 256 + tid;
                int r = idx >> 4, c = idx & 15;
                CP_ASYNC16(dstb + r * 256 + ((c ^ (r & 7)) << 4), srcb + (size_t)idx * 16);
            }
            CP_COMMIT();
        }

        uint32_t bbuf = sB + (uint32_t)(it & 1) * 32768u;
        float acc[2][4][4];
#pragma unroll
        for (int mt = 0; mt < 2; mt++)
#pragma unroll
            for (int nt = 0; nt < 4; nt++)
#pragma unroll
                for (int k = 0; k < 4; k++) acc[mt][nt][k] = 0.f;

#pragma unroll
        for (int ks = 0; ks < 8; ks++) {
            uint32_t c16 = (uint32_t)(2 * ks + hi);
            uint32_t b[2][4];
#pragma unroll
            for (int np = 0; np < 2; np++)
                ldsm4(b[np][0], b[np][1], b[np][2], b[np][3],
                      bbuf + bOff[np] + ((c16 ^ bSw[np]) << 4));
            uint32_t a[2][4];
            if (ks < 4) {
#pragma unroll
                for (int mt = 0; mt < 2; mt++)
#pragma unroll
                    for (int k = 0; k < 4; k++) a[mt][k] = areg[mt][ks][k];
            } else {
#pragma unroll
                for (int mt = 0; mt < 2; mt++)
                    ldsm4(a[mt][0], a[mt][1], a[mt][2], a[mt][3],
                          aAddr[mt] + ((c16 ^ aSw[mt]) << 4));
            }
#pragma unroll
            for (int mt = 0; mt < 2; mt++)
#pragma unroll
                for (int nt = 0; nt < 4; nt++) {
                    int np = nt >> 1, odd = nt & 1;
                    mma16816(acc[mt][nt], a[mt][0], a[mt][1], a[mt][2], a[mt][3],
                             b[np][odd], b[np][2 + odd]);
                }
        }

        // epilogue: streaming float2 stores
#pragma unroll
        for (int mt = 0; mt < 2; mt++) {
            int t0 = strip * 64 + wm * 32 + mt * 16 + (l >> 2);
#pragma unroll
            for (int nt = 0; nt < 4; nt++) {
                int s = it * 128 + wn * 32 + nt * 8 + 2 * (l & 3);
                float2 v0, v1;
                v0.x = __fmaf_rn(alpha, acc[mt][nt][0], ct[mt][0]);
                v0.y = __fmaf_rn(alpha, acc[mt][nt][1], ct[mt][0]);
                v1.x = __fmaf_rn(alpha, acc[mt][nt][2], ct[mt][1]);
                v1.y = __fmaf_rn(alpha, acc[mt][nt][3], ct[mt][1]);
                __stcs(reinterpret_cast<float2*>(outp + (size_t)t0 * 1024 + s), v0);
                __stcs(reinterpret_cast<float2*>(outp + (size_t)(t0 + 8) * 1024 + s), v1);
            }
        }

        // next tile landed + all readers done with this B buffer
        CP_WAIT0();
        __syncthreads();
    }
}

// ---------------- launch ----------------
extern "C" void kernel_launch(void* const* d_in, const int* in_sizes, int n_in,
                              void* d_out, int out_size) {
    const float* x1 = (const float*)d_in[0];
    const float* x2 = (const float*)d_in[1];
    const float* mu = (const float*)d_in[2];
    float* out = (float*)d_out;

    cudaFuncSetAttribute(gemm_kernel, cudaFuncAttributeMaxDynamicSharedMemorySize, SMEM_BYTES);

    amax_fused<<<20480, 256>>>(x1, x2, mu);
    quant_fused<<<24576, 256>>>(x1, x2, mu);
    gemm_kernel<<<dim3(16, 128), 256, SMEM_BYTES>>>(out);
}

// round 17
// speedup vs baseline: 1.0595x; 1.0595x over previous
#include <cuda_runtime.h>
#include <cuda_fp16.h>
#include <cstdint>

// ---------------- problem constants ----------------
#define SLABS      128                  // B*H = 4*32
#define TL         1024
#define HD         128
#define SLAB_ELEMS (TL * HD)
#define TOT        (SLABS * SLAB_ELEMS) // 16,777,216 elements

// ---------------- device scratch ----------------
__device__ __align__(16) __half g_q1[TOT];   // quantized x1, row-major [slab][t][k]
__device__ __align__(16) __half g_S [TOT];   // S = q2 @ H_raw, row-major [slab][s][k]
__device__ float     g_c [SLABS * TL];       // c[t] = q1[t,:]·mu
__device__ unsigned  g_amax1[SLABS];
__device__ unsigned  g_amax2[SLABS];

// ---------------- PTX helpers ----------------
__device__ __forceinline__ uint32_t smem_u32(const void* p) {
    uint32_t a;
    asm("{ .reg .u64 t; cvta.to.shared.u64 t, %1; cvt.u32.u64 %0, t; }" : "=r"(a) : "l"(p));
    return a;
}
#define CP_ASYNC16(dst, src) \
    asm volatile("cp.async.cg.shared.global [%0], [%1], 16;" :: "r"((uint32_t)(dst)), "l"(src))
#define CP_COMMIT() asm volatile("cp.async.commit_group;" ::: "memory")
#define CP_WAIT0()  asm volatile("cp.async.wait_group 0;"  ::: "memory")

__device__ __forceinline__ void ldsm4(uint32_t& r0, uint32_t& r1, uint32_t& r2, uint32_t& r3,
                                      uint32_t addr) {
    asm volatile("ldmatrix.sync.aligned.m8n8.x4.shared.b16 {%0,%1,%2,%3}, [%4];"
                 : "=r"(r0), "=r"(r1), "=r"(r2), "=r"(r3) : "r"(addr));
}
__device__ __forceinline__ void mma16816(float c[4], uint32_t a0, uint32_t a1, uint32_t a2,
                                         uint32_t a3, uint32_t b0, uint32_t b1) {
    asm volatile(
        "mma.sync.aligned.m16n8k16.row.col.f32.f16.f16.f32 "
        "{%0,%1,%2,%3}, {%4,%5,%6,%7}, {%8,%9}, {%0,%1,%2,%3};"
        : "+f"(c[0]), "+f"(c[1]), "+f"(c[2]), "+f"(c[3])
        : "r"(a0), "r"(a1), "r"(a2), "r"(a3), "r"(b0), "r"(b1));
}

// ---------------- reduction helpers ----------------
__device__ __forceinline__ float warp_max(float m) {
#pragma unroll
    for (int s = 16; s; s >>= 1) m = fmaxf(m, __shfl_xor_sync(0xffffffffu, m, s));
    return m;
}
__device__ __forceinline__ float warp_sum(float v) {
#pragma unroll
    for (int s = 16; s; s >>= 1) v += __shfl_xor_sync(0xffffffffu, v, s);
    return v;
}

// FWHT 128, contiguous layout, TWO independent rows interleaved for ILP:
// lane l holds a[k] = rowA[4l+k], b[k] = rowB[4l+k]. FFMA(+/-1) exact.
// The two shuffle chains are independent -> fill each other's SHFL latency.
__device__ __forceinline__ void fwht128c_x2(float a[4], float b[4], int l) {
    float t;
    t = a[0]; a[0] = t + a[1]; a[1] = t - a[1];
    t = a[2]; a[2] = t + a[3]; a[3] = t - a[3];
    t = b[0]; b[0] = t + b[1]; b[1] = t - b[1];
    t = b[2]; b[2] = t + b[3]; b[3] = t - b[3];
    t = a[0]; a[0] = t + a[2]; a[2] = t - a[2];
    t = a[1]; a[1] = t + a[3]; a[3] = t - a[3];
    t = b[0]; b[0] = t + b[2]; b[2] = t - b[2];
    t = b[1]; b[1] = t + b[3]; b[3] = t - b[3];
#pragma unroll
    for (int s = 1; s <= 16; s <<= 1) {
        float sgn = __int_as_float((l & s) ? 0xBF800000u : 0x3F800000u);
#pragma unroll
        for (int k = 0; k < 4; k++) {
            float pa = __shfl_xor_sync(0xffffffffu, a[k], s);
            float pb = __shfl_xor_sync(0xffffffffu, b[k], s);
            a[k] = __fmaf_rn(sgn, a[k], pa);
            b[k] = __fmaf_rn(sgn, b[k], pb);
        }
    }
}

// ---------------- prep kernels ----------------
__global__ void init_kernel() {
    int t = threadIdx.x;
    if (t < SLABS) { g_amax1[t] = 0u; g_amax2[t] = 0u; }
}

// fused amax: blocks [0,4096) -> amax1(x1); [4096,12288) -> amax2 (16 rows/block)
__global__ __launch_bounds__(256) void amax_fused(const float* __restrict__ x1,
                                                  const float* __restrict__ x2,
                                                  const float* __restrict__ mu) {
    __shared__ float red[8];
    int bid = blockIdx.x;
    int l = threadIdx.x & 31;
    if (bid < 4096) {
        int slab = bid >> 5, part = bid & 31;
        const float4* p = reinterpret_cast<const float4*>(x1 + (size_t)slab * SLAB_ELEMS)
                          + (size_t)part * 1024 + threadIdx.x;
        float m = 0.f;
#pragma unroll
        for (int i = 0; i < 4; i++) {
            float4 v = p[i * 256];
            m = fmaxf(m, fmaxf(fmaxf(fabsf(v.x), fabsf(v.y)), fmaxf(fabsf(v.z), fabsf(v.w))));
        }
        m = warp_max(m);
        if (l == 0) red[threadIdx.x >> 5] = m;
        __syncthreads();
        if (threadIdx.x == 0) {
            float mm = red[0];
#pragma unroll
            for (int i = 1; i < 8; i++) mm = fmaxf(mm, red[i]);
            atomicMax(&g_amax1[slab], __float_as_uint(mm));
        }
    } else {
        // 16 rows/block, 2 rows/warp, dual FWHT
        int r0 = ((bid - 4096) << 4) + ((threadIdx.x >> 5) << 1);
        int slab = r0 >> 10, h = slab & 31;
        float4 xa = reinterpret_cast<const float4*>(x2 + (size_t)r0 * HD)[l];
        float4 xb = reinterpret_cast<const float4*>(x2 + (size_t)(r0 + 1) * HD)[l];
        float4 mv = reinterpret_cast<const float4*>(mu + h * HD)[l];
        float a[4] = { xa.x - mv.x, xa.y - mv.y, xa.z - mv.z, xa.w - mv.w };
        float b[4] = { xb.x - mv.x, xb.y - mv.y, xb.z - mv.z, xb.w - mv.w };
        fwht128c_x2(a, b, l);
        float inv = __fdiv_rn(1.0f, __fsqrt_rn(128.0f));
        float m = 0.f;
#pragma unroll
        for (int k = 0; k < 4; k++) {
            m = fmaxf(m, fabsf(__fmul_rn(a[k], inv)));
            m = fmaxf(m, fabsf(__fmul_rn(b[k], inv)));
        }
        m = warp_max(m);
        if (l == 0) red[threadIdx.x >> 5] = m;
        __syncthreads();
        if (threadIdx.x == 0) {
            float mm = red[0];
#pragma unroll
            for (int i = 1; i < 8; i++) mm = fmaxf(mm, red[i]);
            atomicMax(&g_amax2[slab], __float_as_uint(mm));
        }
    }
}

// fused quant: blocks [0,8192) -> quant1 (2 rows/warp);
//              [8192,16384) -> quant2S (16 rows/block, 2 rows/warp, dual FWHT)
__global__ __launch_bounds__(256) void quant_fused(const float* __restrict__ x1,
                                                   const float* __restrict__ x2,
                                                   const float* __restrict__ mu) {
    int bid = blockIdx.x;
    int l = threadIdx.x & 31;
    if (bid < 8192) {
        int r0 = (bid << 4) + ((threadIdx.x >> 5) << 1);
        int slab = r0 >> 10, h = slab & 31;
        float rs = __fdiv_rn(127.0f, fmaxf(__uint_as_float(g_amax1[slab]), 1e-8f));
        float4 v0 = reinterpret_cast<const float4*>(x1 + (size_t)r0 * HD)[l];
        float4 v1 = reinterpret_cast<const float4*>(x1 + (size_t)(r0 + 1) * HD)[l];
        float4 m = reinterpret_cast<const float4*>(mu + h * HD)[l];
        float4 q0, q1;
        q0.x = fminf(fmaxf(rintf(__fmul_rn(v0.x, rs)), -128.f), 127.f);
        q0.y = fminf(fmaxf(rintf(__fmul_rn(v0.y, rs)), -128.f), 127.f);
        q0.z = fminf(fmaxf(rintf(__fmul_rn(v0.z, rs)), -128.f), 127.f);
        q0.w = fminf(fmaxf(rintf(__fmul_rn(v0.w, rs)), -128.f), 127.f);
        q1.x = fminf(fmaxf(rintf(__fmul_rn(v1.x, rs)), -128.f), 127.f);
        q1.y = fminf(fmaxf(rintf(__fmul_rn(v1.y, rs)), -128.f), 127.f);
        q1.z = fminf(fmaxf(rintf(__fmul_rn(v1.z, rs)), -128.f), 127.f);
        q1.w = fminf(fmaxf(rintf(__fmul_rn(v1.w, rs)), -128.f), 127.f);
        float p0 = __fmaf_rn(q0.x, m.x, __fmaf_rn(q0.y, m.y, __fmaf_rn(q0.z, m.z, q0.w * m.w)));
        float p1 = __fmaf_rn(q1.x, m.x, __fmaf_rn(q1.y, m.y, __fmaf_rn(q1.z, m.z, q1.w * m.w)));
        p0 = warp_sum(p0);
        p1 = warp_sum(p1);
        if (l == 0) { g_c[r0] = p0; g_c[r0 + 1] = p1; }
        __half2 a0 = __floats2half2_rn(q0.x, q0.y), a1 = __floats2half2_rn(q0.z, q0.w);
        __half2 b0 = __floats2half2_rn(q1.x, q1.y), b1 = __floats2half2_rn(q1.z, q1.w);
        uint2 w0, w1;
        w0.x = *reinterpret_cast<uint32_t*>(&a0); w0.y = *reinterpret_cast<uint32_t*>(&a1);
        w1.x = *reinterpret_cast<uint32_t*>(&b0); w1.y = *reinterpret_cast<uint32_t*>(&b1);
        reinterpret_cast<uint2*>(g_q1 + (size_t)r0 * HD)[l] = w0;
        reinterpret_cast<uint2*>(g_q1 + (size_t)(r0 + 1) * HD)[l] = w1;
    } else {
        int r0 = ((bid - 8192) << 4) + ((threadIdx.x >> 5) << 1);
        int slab = r0 >> 10, h = slab & 31;
        float rs = __fdiv_rn(7.0f, fmaxf(__uint_as_float(g_amax2[slab]), 1e-8f));
        float4 xa = reinterpret_cast<const float4*>(x2 + (size_t)r0 * HD)[l];
        float4 xb = reinterpret_cast<const float4*>(x2 + (size_t)(r0 + 1) * HD)[l];
        float4 mv = reinterpret_cast<const float4*>(mu + h * HD)[l];
        float a[4] = { xa.x - mv.x, xa.y - mv.y, xa.z - mv.z, xa.w - mv.w };
        float b[4] = { xb.x - mv.x, xb.y - mv.y, xb.z - mv.z, xb.w - mv.w };
        fwht128c_x2(a, b, l);
        float inv = __fdiv_rn(1.0f, __fsqrt_rn(128.0f));
        float f = __fmul_rn(inv, rs);
#pragma unroll
        for (int k = 0; k < 4; k++) {
            a[k] = fminf(fmaxf(rintf(__fmul_rn(a[k], f)), -8.f), 7.f);
            b[k] = fminf(fmaxf(rintf(__fmul_rn(b[k], f)), -8.f), 7.f);
        }
        fwht128c_x2(a, b, l);   // S integers, |S| <= 1024; lanes contiguous
        __half2 pa0 = __floats2half2_rn(a[0], a[1]);
        __half2 pa1 = __floats2half2_rn(a[2], a[3]);
        __half2 pb0 = __floats2half2_rn(b[0], b[1]);
        __half2 pb1 = __floats2half2_rn(b[2], b[3]);
        uint2 wa, wb;
        wa.x = *reinterpret_cast<uint32_t*>(&pa0); wa.y = *reinterpret_cast<uint32_t*>(&pa1);
        wb.x = *reinterpret_cast<uint32_t*>(&pb0); wb.y = *reinterpret_cast<uint32_t*>(&pb1);
        reinterpret_cast<uint2*>(g_S + (size_t)r0 * HD)[l] = wa;
        reinterpret_cast<uint2*>(g_S + (size_t)(r0 + 1) * HD)[l] = wb;
    }
}

// ---------------- GEMM: out[t,s] = alpha*(q1 @ S^T) + scale1*c[t] ----------------
// R8 configuration (measured best: 146.2-146.8us). FROZEN.
#define SMEM_BYTES (81920 + 1024)

__global__ __launch_bounds__(256, 2) void gemm_kernel(float* __restrict__ out) {
    extern __shared__ uint8_t smem_raw[];
    uint32_t sbase = (smem_u32(smem_raw) + 1023u) & ~1023u;
    uint32_t sA = sbase;                       // 16KB
    uint32_t sB = sbase + 16384u;              // 2 x 32KB

    int tid = threadIdx.x, l = tid & 31, wid = tid >> 5;
    int wm = wid >> 2, wn = wid & 3;           // wm 0..1, wn 0..3
    int strip = blockIdx.x, slab = blockIdx.y;

    const uint8_t* gA = reinterpret_cast<const uint8_t*>(g_q1)
                      + ((size_t)slab << 18) + (size_t)strip * 16384u;
    const uint8_t* gB = reinterpret_cast<const uint8_t*>(g_S) + ((size_t)slab << 18);

    // ---- stage A (64 rows x 256B) + B0 ----
#pragma unroll
    for (int p = 0; p < 4; p++) {
        int idx = p * 256 + tid;
        int r = idx >> 4, c = idx & 15;
        CP_ASYNC16(sA + r * 256 + ((c ^ (r & 7)) << 4), gA + (size_t)idx * 16);
    }
#pragma unroll
    for (int p = 0; p < 8; p++) {
        int idx = p * 256 + tid;
        int r = idx >> 4, c = idx & 15;
        CP_ASYNC16(sB + r * 256 + ((c ^ (r & 7)) << 4), gB + (size_t)idx * 16);
    }
    CP_COMMIT();

    // ---- scales / per-row correction ----
    float scale1 = __fdiv_rn(fmaxf(__uint_as_float(g_amax1[slab]), 1e-8f), 127.0f);
    float scale2 = __fdiv_rn(fmaxf(__uint_as_float(g_amax2[slab]), 1e-8f), 7.0f);
    float alpha  = scale1 * scale2 * __fdiv_rn(1.0f, __fsqrt_rn(128.0f));

    float ct[2][2];
#pragma unroll
    for (int mt = 0; mt < 2; mt++) {
        int t0 = strip * 64 + wm * 32 + mt * 16 + (l >> 2);
        ct[mt][0] = scale1 * __ldg(&g_c[slab * 1024 + t0]);
        ct[mt][1] = scale1 * __ldg(&g_c[slab * 1024 + t0 + 8]);
    }

    int hi = (l >> 4);
    uint32_t aAddr[2], aSw[2];
#pragma unroll
    for (int mt = 0; mt < 2; mt++) {
        int r = wm * 32 + mt * 16 + (l & 15);
        aAddr[mt] = sA + r * 256;
        aSw[mt] = (uint32_t)(r & 7);
    }
    uint32_t bOff[2], bSw[2];
#pragma unroll
    for (int np = 0; np < 2; np++) {
        int r = wn * 32 + np * 16 + (l & 15);
        bOff[np] = (uint32_t)(r * 256);
        bSw[np] = (uint32_t)(r & 7);
    }

    // ---- wait for A+B0; hoist A fragments for ksteps 0..3 (32 regs) ----
    CP_WAIT0();
    __syncthreads();

    uint32_t areg[2][4][4];
#pragma unroll
    for (int mt = 0; mt < 2; mt++)
#pragma unroll
        for (int ks = 0; ks < 4; ks++) {
            uint32_t c16 = (uint32_t)(2 * ks + hi);
            ldsm4(areg[mt][ks][0], areg[mt][ks][1], areg[mt][ks][2], areg[mt][ks][3],
                  aAddr[mt] + ((c16 ^ aSw[mt]) << 4));
        }

    float* outp = out + ((size_t)slab << 20);

    for (int it = 0; it < 8; it++) {
        // prefetch next B tile into the other buffer
        if (it + 1 < 8) {
            uint32_t dstb = sB + (uint32_t)((it + 1) & 1) * 32768u;
            const uint8_t* srcb = gB + ((size_t)(it + 1) << 15);
#pragma unroll
            for (int p = 0; p < 8; p++) {
                int idx = p * 256 + tid;
                int r = idx >> 4, c = idx & 15;
                CP_ASYNC16(dstb + r * 256 + ((c ^ (r & 7)) << 4), srcb + (size_t)idx * 16);
            }
            CP_COMMIT();
        }

        uint32_t bbuf = sB + (uint32_t)(it & 1) * 32768u;
        float acc[2][4][4];
#pragma unroll
        for (int mt = 0; mt < 2; mt++)
#pragma unroll
            for (int nt = 0; nt < 4; nt++)
#pragma unroll
                for (int k = 0; k < 4; k++) acc[mt][nt][k] = 0.f;

#pragma unroll
        for (int ks = 0; ks < 8; ks++) {
            uint32_t c16 = (uint32_t)(2 * ks + hi);
            uint32_t b[2][4];
#pragma unroll
            for (int np = 0; np < 2; np++)
                ldsm4(b[np][0], b[np][1], b[np][2], b[np][3],
                      bbuf + bOff[np] + ((c16 ^ bSw[np]) << 4));
            uint32_t a[2][4];
            if (ks < 4) {
#pragma unroll
                for (int mt = 0; mt < 2; mt++)
#pragma unroll
                    for (int k = 0; k < 4; k++) a[mt][k] = areg[mt][ks][k];
            } else {
#pragma unroll
                for (int mt = 0; mt < 2; mt++)
                    ldsm4(a[mt][0], a[mt][1], a[mt][2], a[mt][3],
                          aAddr[mt] + ((c16 ^ aSw[mt]) << 4));
            }
#pragma unroll
            for (int mt = 0; mt < 2; mt++)
#pragma unroll
                for (int nt = 0; nt < 4; nt++) {
                    int np = nt >> 1, odd = nt & 1;
                    mma16816(acc[mt][nt], a[mt][0], a[mt][1], a[mt][2], a[mt][3],
                             b[np][odd], b[np][2 + odd]);
                }
        }

        // epilogue: streaming float2 stores
#pragma unroll
        for (int mt = 0; mt < 2; mt++) {
            int t0 = strip * 64 + wm * 32 + mt * 16 + (l >> 2);
#pragma unroll
            for (int nt = 0; nt < 4; nt++) {
                int s = it * 128 + wn * 32 + nt * 8 + 2 * (l & 3);
                float2 v0, v1;
                v0.x = __fmaf_rn(alpha, acc[mt][nt][0], ct[mt][0]);
                v0.y = __fmaf_rn(alpha, acc[mt][nt][1], ct[mt][0]);
                v1.x = __fmaf_rn(alpha, acc[mt][nt][2], ct[mt][1]);
                v1.y = __fmaf_rn(alpha, acc[mt][nt][3], ct[mt][1]);
                __stcs(reinterpret_cast<float2*>(outp + (size_t)t0 * 1024 + s), v0);
                __stcs(reinterpret_cast<float2*>(outp + (size_t)(t0 + 8) * 1024 + s), v1);
            }
        }

        // next tile landed + all readers done with this B buffer
        CP_WAIT0();
        __syncthreads();
    }
}

// ---------------- launch ----------------
extern "C" void kernel_launch(void* const* d_in, const int* in_sizes, int n_in,
                              void* d_out, int out_size) {
    const float* x1 = (const float*)d_in[0];
    const float* x2 = (const float*)d_in[1];
    const float* mu = (const float*)d_in[2];
    float* out = (float*)d_out;

    cudaFuncSetAttribute(gemm_kernel, cudaFuncAttributeMaxDynamicSharedMemorySize, SMEM_BYTES);

    init_kernel<<<1, 128>>>();
    amax_fused<<<12288, 256>>>(x1, x2, mu);
    quant_fused<<<16384, 256>>>(x1, x2, mu);
    gemm_kernel<<<dim3(16, 128), 256, SMEM_BYTES>>>(out);
}